// round 4
// baseline (speedup 1.0000x reference)
#include <cuda_runtime.h>

#define DEP   5
#define TOTAL 4096
#define SLOT  5120
#define NSEG  16

// ---------------- fused-path config ----------------
#define CHUNK    128            // slots per CTA
#define NCHUNK   (SLOT / CHUNK) // 40
#define MAXTOK   384            // cached token rows per CTA (expected max ~310)
#define FWARPS   16
#define FTHREADS (FWARPS * 32)  // 512

#define SMEM_ROWS   (MAXTOK * CHUNK)
#define SMEM_WMEM   (FWARPS * CHUNK)
#define SMEM_FLOATS (SMEM_ROWS + SMEM_WMEM + CHUNK)
#define SMEM_BYTES  (SMEM_FLOATS * 4)   // 205,312 B < 227 KB opt-in limit

// ---------------- device scratch ----------------
__device__ float g_br[TOTAL * DEP];            // basic_read accumulator
__device__ int   g_seg_start[NSEG];
__device__ int   g_seg_cnt[NSEG];
__device__ float g_mem[NSEG * DEP * SLOT];     // fallback-path scratch (1.6 MB)

// ===========================================================================
// shared init kernels
// ===========================================================================
__global__ void initA_kernel() {
    int i = blockIdx.x * blockDim.x + threadIdx.x;
    if (i < TOTAL * DEP) g_br[i] = 0.f;
    if (i < NSEG) { g_seg_cnt[i] = 0; g_seg_start[i] = 0; }
}

__global__ void initB_kernel(const int* __restrict__ seg) {
    int t = blockIdx.x * blockDim.x + threadIdx.x;
    if (t >= TOTAL) return;
    int s = seg[t];
    atomicAdd(&g_seg_cnt[s], 1);
    if (t == 0 || seg[t - 1] != s) g_seg_start[s] = t;
}

// ===========================================================================
// FUSED PATH: single read of addr. grid(NCHUNK, DEP, NSEG), 512 thr, 200 KB smem
// ===========================================================================
__global__ void fused_kernel(const float* __restrict__ addr,
                             const float* __restrict__ emb,
                             const float* __restrict__ freq,
                             const float* __restrict__ mm) {
    extern __shared__ float sm[];
    float* rows = sm;                    // [MAXTOK][CHUNK]
    float* wmem = sm + SMEM_ROWS;        // [FWARPS][CHUNK]
    float* memc = wmem + SMEM_WMEM;      // [CHUNK]

    const int s0 = blockIdx.x * CHUNK;
    const int d  = blockIdx.y;
    const int b  = blockIdx.z;

    const int t_start = g_seg_start[b];
    const int n       = g_seg_cnt[b];
    if (n == 0) return;                  // uniform per block — no divergent syncs

    const int w    = threadIdx.x >> 5;
    const int lane = threadIdx.x & 31;

    const float* abase = addr + (size_t)d * TOTAL * SLOT + s0 + lane * 4;

    // ---- pass 1: stream tokens, cache rows in smem, accumulate write-sum ----
    float4 acc = make_float4(0.f, 0.f, 0.f, 0.f);
    #pragma unroll 4
    for (int tl = w; tl < n; tl += FWARPS) {
        const int t = t_start + tl;
        const float f = __ldg(&emb[t * DEP + d]) * __ldg(&freq[t]);
        float4 a = *reinterpret_cast<const float4*>(abase + (size_t)t * SLOT);
        if (tl < MAXTOK)
            *reinterpret_cast<float4*>(rows + tl * CHUNK + lane * 4) = a;
        acc.x = fmaf(a.x, f, acc.x);
        acc.y = fmaf(a.y, f, acc.y);
        acc.z = fmaf(a.z, f, acc.z);
        acc.w = fmaf(a.w, f, acc.w);
    }
    *reinterpret_cast<float4*>(wmem + w * CHUNK + lane * 4) = acc;
    __syncthreads();

    // ---- reduce across warps, add memory_matrix chunk ----
    if (threadIdx.x < CHUNK) {
        float s = mm[((size_t)b * DEP + d) * SLOT + s0 + threadIdx.x];
        #pragma unroll
        for (int i = 0; i < FWARPS; ++i) s += wmem[i * CHUNK + threadIdx.x];
        memc[threadIdx.x] = s;
    }
    __syncthreads();

    // ---- pass 2: per-token dot of cached row against mem chunk ----
    const float4 mv = *reinterpret_cast<const float4*>(memc + lane * 4);
    #pragma unroll 4
    for (int tl = w; tl < n; tl += FWARPS) {
        float4 a;
        if (tl < MAXTOK) {
            a = *reinterpret_cast<const float4*>(rows + tl * CHUNK + lane * 4);
        } else {  // overflow fallback: re-read (rare; L2 hit)
            a = *reinterpret_cast<const float4*>(abase + (size_t)(t_start + tl) * SLOT);
        }
        float v = a.x * mv.x + a.y * mv.y + a.z * mv.z + a.w * mv.w;
        #pragma unroll
        for (int o = 16; o > 0; o >>= 1) v += __shfl_down_sync(0xFFFFFFFFu, v, o);
        if (lane == 0) atomicAdd(&g_br[(t_start + tl) * DEP + d], v);
    }
}

// ===========================================================================
// FALLBACK PATH (proven 143 us): scatter into g_mem, then gather
// ===========================================================================
__global__ void init_mem_kernel(const float* __restrict__ mm) {
    int i = blockIdx.x * blockDim.x + threadIdx.x;
    if (i < NSEG * DEP * SLOT) g_mem[i] = mm[i];
}

#define T_CHUNK 32
#define SCATTER_THREADS 128

__global__ void scatter_kernel(const float* __restrict__ addr,
                               const float* __restrict__ emb,
                               const float* __restrict__ freq,
                               const int*   __restrict__ seg) {
    __shared__ float s_f[T_CHUNK];
    __shared__ int   s_seg[T_CHUNK];

    const int d  = blockIdx.y;
    const int t0 = blockIdx.z * T_CHUNK;
    const int s0 = blockIdx.x * (SCATTER_THREADS * 4) + threadIdx.x * 4;

    if (threadIdx.x < T_CHUNK) {
        int t = t0 + threadIdx.x;
        s_f[threadIdx.x]   = emb[t * DEP + d] * freq[t];
        s_seg[threadIdx.x] = seg[t];
    }
    __syncthreads();

    const float* base = addr + (size_t)d * TOTAL * SLOT + s0;

    float4 acc = make_float4(0.f, 0.f, 0.f, 0.f);
    int cur = s_seg[0];

    #pragma unroll 4
    for (int i = 0; i < T_CHUNK; ++i) {
        int sg = s_seg[i];
        if (sg != cur) {
            float* g = &g_mem[((size_t)cur * DEP + d) * SLOT + s0];
            atomicAdd(g + 0, acc.x); atomicAdd(g + 1, acc.y);
            atomicAdd(g + 2, acc.z); atomicAdd(g + 3, acc.w);
            acc = make_float4(0.f, 0.f, 0.f, 0.f);
            cur = sg;
        }
        float  f = s_f[i];
        float4 a = *reinterpret_cast<const float4*>(base + (size_t)(t0 + i) * SLOT);
        acc.x = fmaf(a.x, f, acc.x);
        acc.y = fmaf(a.y, f, acc.y);
        acc.z = fmaf(a.z, f, acc.z);
        acc.w = fmaf(a.w, f, acc.w);
    }
    {
        float* g = &g_mem[((size_t)cur * DEP + d) * SLOT + s0];
        atomicAdd(g + 0, acc.x); atomicAdd(g + 1, acc.y);
        atomicAdd(g + 2, acc.z); atomicAdd(g + 3, acc.w);
    }
}

#define GATHER_THREADS 256

__global__ void gather_kernel(const float* __restrict__ addr,
                              const int*   __restrict__ seg) {
    const int t  = blockIdx.x;
    const int sg = seg[t];

    float sums[DEP];
    #pragma unroll
    for (int d = 0; d < DEP; ++d) {
        const float4* a = reinterpret_cast<const float4*>(
            addr + ((size_t)d * TOTAL + t) * SLOT);
        const float4* m = reinterpret_cast<const float4*>(
            g_mem + ((size_t)sg * DEP + d) * SLOT);
        float s = 0.f;
        #pragma unroll
        for (int i = 0; i < SLOT / 4 / GATHER_THREADS; ++i) {
            int idx = i * GATHER_THREADS + threadIdx.x;
            float4 av = a[idx];
            float4 mv = m[idx];
            s = fmaf(av.x, mv.x, s); s = fmaf(av.y, mv.y, s);
            s = fmaf(av.z, mv.z, s); s = fmaf(av.w, mv.w, s);
        }
        sums[d] = s;
    }

    int lane = threadIdx.x & 31;
    #pragma unroll
    for (int d = 0; d < DEP; ++d) {
        float v = sums[d];
        #pragma unroll
        for (int o = 16; o > 0; o >>= 1) v += __shfl_down_sync(0xFFFFFFFFu, v, o);
        if (lane == 0) atomicAdd(&g_br[t * DEP + d], v);
    }
}

// ===========================================================================
// epilogue: cm_info = br/emb, row-min, write outputs
// layout: [cm_readhead 4096][cm_info 4096*5][basic_read 4096*5]
// ===========================================================================
__global__ void epilogue_kernel(const float* __restrict__ emb,
                                float* __restrict__ out) {
    int t = blockIdx.x * blockDim.x + threadIdx.x;
    if (t >= TOTAL) return;
    float mn = INFINITY;
    #pragma unroll
    for (int d = 0; d < DEP; ++d) {
        float br = g_br[t * DEP + d];
        float ci = br / emb[t * DEP + d];
        mn = fminf(mn, ci);
        out[TOTAL + t * DEP + d]               = ci;
        out[TOTAL + TOTAL * DEP + t * DEP + d] = br;
    }
    out[t] = mn;
}

// ===========================================================================
extern "C" void kernel_launch(void* const* d_in, const int* in_sizes, int n_in,
                              void* d_out, int out_size) {
    const float* addr = (const float*)d_in[0];  // [5, 4096, 5120]
    const float* emb  = (const float*)d_in[1];  // [4096, 5]
    const float* freq = (const float*)d_in[2];  // [4096]
    const float* mm   = (const float*)d_in[3];  // [16, 5, 5120]
    const int*   seg  = (const int*)  d_in[4];  // [4096]
    float* out = (float*)d_out;

    // Opt in to >48KB dynamic smem. Deterministic per machine; if it fails,
    // take the proven fallback path instead of launching a broken config.
    cudaError_t attr_err = cudaFuncSetAttribute(
        fused_kernel, cudaFuncAttributeMaxDynamicSharedMemorySize, SMEM_BYTES);

    initA_kernel<<<(TOTAL * DEP + 255) / 256, 256>>>();

    if (attr_err == cudaSuccess) {
        // -------- fused path: addr read once (~422 MB total LTS traffic) ----
        initB_kernel<<<(TOTAL + 255) / 256, 256>>>(seg);
        dim3 grid(NCHUNK, DEP, NSEG);  // (40, 5, 16)
        fused_kernel<<<grid, FTHREADS, SMEM_BYTES>>>(addr, emb, freq, mm);
    } else {
        // -------- fallback path: scatter + gather (addr read twice) --------
        init_mem_kernel<<<(NSEG * DEP * SLOT + 255) / 256, 256>>>(mm);
        dim3 sg_grid(SLOT / (SCATTER_THREADS * 4), DEP, TOTAL / T_CHUNK);
        scatter_kernel<<<sg_grid, SCATTER_THREADS>>>(addr, emb, freq, seg);
        gather_kernel<<<TOTAL, GATHER_THREADS>>>(addr, seg);
    }

    epilogue_kernel<<<(TOTAL + 255) / 256, 256>>>(emb, out);
}